// round 2
// baseline (speedup 1.0000x reference)
#include <cuda_runtime.h>
#include <math_constants.h>

#define BM 128
#define BN 128
#define BK 16
#define TM 8
#define TN 8
#define SA 132   // padded smem row stride (floats): multiple of 4 -> LDS.128 stays 16B-aligned

// 256 threads: 16 (tx over N) x 16 (ty over M)
__global__ __launch_bounds__(256, 1)
void mam_dense_kernel(const float* __restrict__ A,   // [M, K]
                      const float* __restrict__ W,   // [N, K]
                      const float* __restrict__ bias,// [N]
                      float* __restrict__ C,         // [M, N]
                      int M, int N, int K)
{
    __shared__ float As[2][BK * SA];  // As[buf][k*SA + m]
    __shared__ float Bs[2][BK * SA];  // Bs[buf][k*SA + n]

    const int tid = threadIdx.x;
    const int tx  = tid & 15;   // output-column group
    const int ty  = tid >> 4;   // output-row group
    const int bm  = blockIdx.y * BM;
    const int bn  = blockIdx.x * BN;

    // Global-load mapping: 256 threads cover a 128x16 tile as 2 float4 each.
    const int lrow = tid >> 2;        // 0..63
    const int lcol = (tid & 3) * 4;   // 0,4,8,12  (k offset within tile)

    const float* Aptr = A + (size_t)(bm + lrow) * K + lcol;
    const float* Wptr = W + (size_t)(bn + lrow) * K + lcol;
    const size_t rowskip = (size_t)64 * K;

    float4 pa0, pa1, pb0, pb1;

    // ---- accumulators ----
    float mx[TM][TN], mn[TM][TN];
#pragma unroll
    for (int i = 0; i < TM; ++i)
#pragma unroll
        for (int j = 0; j < TN; ++j) {
            mx[i][j] = -CUDART_INF_F;
            mn[i][j] =  CUDART_INF_F;
        }

    // ---- prologue: load tile 0 into buf 0 ----
    pa0 = *(const float4*)(Aptr);
    pa1 = *(const float4*)(Aptr + rowskip);
    pb0 = *(const float4*)(Wptr);
    pb1 = *(const float4*)(Wptr + rowskip);
    {
        float* as = As[0]; float* bs = Bs[0];
        as[(lcol + 0) * SA + lrow] = pa0.x;
        as[(lcol + 1) * SA + lrow] = pa0.y;
        as[(lcol + 2) * SA + lrow] = pa0.z;
        as[(lcol + 3) * SA + lrow] = pa0.w;
        as[(lcol + 0) * SA + lrow + 64] = pa1.x;
        as[(lcol + 1) * SA + lrow + 64] = pa1.y;
        as[(lcol + 2) * SA + lrow + 64] = pa1.z;
        as[(lcol + 3) * SA + lrow + 64] = pa1.w;
        bs[(lcol + 0) * SA + lrow] = pb0.x;
        bs[(lcol + 1) * SA + lrow] = pb0.y;
        bs[(lcol + 2) * SA + lrow] = pb0.z;
        bs[(lcol + 3) * SA + lrow] = pb0.w;
        bs[(lcol + 0) * SA + lrow + 64] = pb1.x;
        bs[(lcol + 1) * SA + lrow + 64] = pb1.y;
        bs[(lcol + 2) * SA + lrow + 64] = pb1.z;
        bs[(lcol + 3) * SA + lrow + 64] = pb1.w;
    }
    __syncthreads();

    const int nTiles = K / BK;

    for (int t = 0; t < nTiles; ++t) {
        const int buf = t & 1;

        // Prefetch next tile into registers (latency hidden by compute below).
        if (t + 1 < nTiles) {
            const int k0 = (t + 1) * BK;
            pa0 = *(const float4*)(Aptr + k0);
            pa1 = *(const float4*)(Aptr + rowskip + k0);
            pb0 = *(const float4*)(Wptr + k0);
            pb1 = *(const float4*)(Wptr + rowskip + k0);
        }

        // ---- compute on buf ----
        const float* as = As[buf];
        const float* bs = Bs[buf];
#pragma unroll 8
        for (int k = 0; k < BK; ++k) {
            float a[TM], b[TN];
            *(float4*)&a[0] = *(const float4*)&as[k * SA + ty * TM];
            *(float4*)&a[4] = *(const float4*)&as[k * SA + ty * TM + 4];
            *(float4*)&b[0] = *(const float4*)&bs[k * SA + tx * TN];
            *(float4*)&b[4] = *(const float4*)&bs[k * SA + tx * TN + 4];
#pragma unroll
            for (int i = 0; i < TM; ++i)
#pragma unroll
                for (int j = 0; j < TN; ++j) {
                    float p = a[i] * b[j];
                    mx[i][j] = fmaxf(mx[i][j], p);
                    mn[i][j] = fminf(mn[i][j], p);
                }
        }

        // ---- stage next tile into the other buffer ----
        if (t + 1 < nTiles) {
            float* asw = As[buf ^ 1]; float* bsw = Bs[buf ^ 1];
            asw[(lcol + 0) * SA + lrow] = pa0.x;
            asw[(lcol + 1) * SA + lrow] = pa0.y;
            asw[(lcol + 2) * SA + lrow] = pa0.z;
            asw[(lcol + 3) * SA + lrow] = pa0.w;
            asw[(lcol + 0) * SA + lrow + 64] = pa1.x;
            asw[(lcol + 1) * SA + lrow + 64] = pa1.y;
            asw[(lcol + 2) * SA + lrow + 64] = pa1.z;
            asw[(lcol + 3) * SA + lrow + 64] = pa1.w;
            bsw[(lcol + 0) * SA + lrow] = pb0.x;
            bsw[(lcol + 1) * SA + lrow] = pb0.y;
            bsw[(lcol + 2) * SA + lrow] = pb0.z;
            bsw[(lcol + 3) * SA + lrow] = pb0.w;
            bsw[(lcol + 0) * SA + lrow + 64] = pb1.x;
            bsw[(lcol + 1) * SA + lrow + 64] = pb1.y;
            bsw[(lcol + 2) * SA + lrow + 64] = pb1.z;
            bsw[(lcol + 3) * SA + lrow + 64] = pb1.w;
            __syncthreads();
        }
    }

    // ---- epilogue: C = mx + mn + bias ----
    const int row0 = bm + ty * TM;
    const int col0 = bn + tx * TN;
    float bv[TN];
    *(float4*)&bv[0] = *(const float4*)&bias[col0];
    *(float4*)&bv[4] = *(const float4*)&bias[col0 + 4];

#pragma unroll
    for (int i = 0; i < TM; ++i) {
        float4 o0, o1;
        o0.x = mx[i][0] + mn[i][0] + bv[0];
        o0.y = mx[i][1] + mn[i][1] + bv[1];
        o0.z = mx[i][2] + mn[i][2] + bv[2];
        o0.w = mx[i][3] + mn[i][3] + bv[3];
        o1.x = mx[i][4] + mn[i][4] + bv[4];
        o1.y = mx[i][5] + mn[i][5] + bv[5];
        o1.z = mx[i][6] + mn[i][6] + bv[6];
        o1.w = mx[i][7] + mn[i][7] + bv[7];
        float* crow = C + (size_t)(row0 + i) * N + col0;
        *(float4*)(crow)     = o0;
        *(float4*)(crow + 4) = o1;
    }
}

extern "C" void kernel_launch(void* const* d_in, const int* in_sizes, int n_in,
                              void* d_out, int out_size)
{
    const float* x    = (const float*)d_in[0];   // [M, K]
    const float* w    = (const float*)d_in[1];   // [N, K]
    const float* bias = (const float*)d_in[2];   // [N]
    float* out = (float*)d_out;

    const int N = in_sizes[2];                  // 1024
    const int K = in_sizes[1] / N;              // 1024
    const int M = in_sizes[0] / K;              // 2048

    dim3 grid(N / BN, M / BM);
    mam_dense_kernel<<<grid, 256>>>(x, w, bias, out, M, N, K);
}

// round 4
// speedup vs baseline: 1.0365x; 1.0365x over previous
#include <cuda_runtime.h>
#include <math_constants.h>

// Persistent-CTA MAM-GEMM: 1024 tiles of 64x32 over exactly 148 CTAs (one per SM).
// Balance: ceil(1024/148)=7 tiles makespan -> 98.8% vs 86.5% for power-of-two grids.

#define TBM 64        // tile rows (M)
#define TBN 32        // tile cols (N)
#define BK  16        // k-slice per stage
#define TM  4         // per-thread rows
#define TN  2         // per-thread cols
#define SA  68        // As padded stride (floats); 68*4=272 bytes, %16==0 -> LDS.128 ok
#define SB  36        // Bs padded stride (floats); 36*4=144 bytes, %16==0 -> LDS.64 ok
#define NUM_SMS 148

__global__ __launch_bounds__(256, 1)
void mam_dense_persistent(const float* __restrict__ A,   // [M, K]
                          const float* __restrict__ W,   // [N, K]
                          const float* __restrict__ bias,// [N]
                          float* __restrict__ C,         // [M, N]
                          int M, int N, int K)
{
    __shared__ float As[2][BK * SA];  // As[buf][k*SA + m]   (transposed: k-major)
    __shared__ float Bs[2][BK * SB];  // Bs[buf][k*SB + n]

    const int tid = threadIdx.x;
    const int tx  = tid & 15;    // 16 col-groups of TN=2
    const int ty  = tid >> 4;    // 16 row-groups of TM=4

    // A-tile staging: 64x16 floats = 1 float4 per thread
    const int ar  = tid >> 2;         // 0..63 (row in tile)
    const int akc = (tid & 3) * 4;    // 0,4,8,12 (k offset)
    // B-tile staging: 32x16 floats = 1 float2 per thread
    const int br  = tid >> 3;         // 0..31 (row in tile)
    const int bkc = (tid & 7) * 2;    // 0,2,...,14 (k offset)

    const int tilesN = N / TBN;                  // 32
    const int nTilesTotal = (M / TBM) * tilesN;  // 1024
    const int nK = K / BK;                       // 64

    for (int t = blockIdx.x; t < nTilesTotal; t += NUM_SMS) {
        const int mi = t / tilesN;
        const int ni = t - mi * tilesN;

        const float* Aptr = A + (size_t)(mi * TBM + ar) * K + akc;
        const float* Wptr = W + (size_t)(ni * TBN + br) * K + bkc;

        // ---- accumulators ----
        float mx[TM][TN], mn[TM][TN];
#pragma unroll
        for (int i = 0; i < TM; ++i)
#pragma unroll
            for (int j = 0; j < TN; ++j) {
                mx[i][j] = -CUDART_INF_F;
                mn[i][j] =  CUDART_INF_F;
            }

        // ---- prologue: stage k-slice 0 into buf 0 ----
        float4 pa = *(const float4*)(Aptr);
        float2 pb = *(const float2*)(Wptr);
        {
            float* as = As[0]; float* bs = Bs[0];
            as[(akc + 0) * SA + ar] = pa.x;
            as[(akc + 1) * SA + ar] = pa.y;
            as[(akc + 2) * SA + ar] = pa.z;
            as[(akc + 3) * SA + ar] = pa.w;
            bs[(bkc + 0) * SB + br] = pb.x;
            bs[(bkc + 1) * SB + br] = pb.y;
        }
        __syncthreads();

        for (int kt = 0; kt < nK; ++kt) {
            const int buf = kt & 1;

            if (kt + 1 < nK) {
                const int k0 = (kt + 1) * BK;
                pa = *(const float4*)(Aptr + k0);
                pb = *(const float2*)(Wptr + k0);
            }

            const float* as = As[buf];
            const float* bs = Bs[buf];
#pragma unroll
            for (int k = 0; k < BK; ++k) {
                float a[TM], b[TN];
                *(float4*)&a[0] = *(const float4*)&as[k * SA + ty * TM];
                *(float2*)&b[0] = *(const float2*)&bs[k * SB + tx * TN];
#pragma unroll
                for (int i = 0; i < TM; ++i)
#pragma unroll
                    for (int j = 0; j < TN; ++j) {
                        float p = a[i] * b[j];
                        mx[i][j] = fmaxf(mx[i][j], p);
                        mn[i][j] = fminf(mn[i][j], p);
                    }
            }

            if (kt + 1 < nK) {
                float* asw = As[buf ^ 1]; float* bsw = Bs[buf ^ 1];
                asw[(akc + 0) * SA + ar] = pa.x;
                asw[(akc + 1) * SA + ar] = pa.y;
                asw[(akc + 2) * SA + ar] = pa.z;
                asw[(akc + 3) * SA + ar] = pa.w;
                bsw[(bkc + 0) * SB + br] = pb.x;
                bsw[(bkc + 1) * SB + br] = pb.y;
                __syncthreads();
            }
        }

        // ---- epilogue: C = mx + mn + bias ----
        const int row0 = mi * TBM + ty * TM;
        const int col0 = ni * TBN + tx * TN;
        float2 bv = *(const float2*)&bias[col0];

#pragma unroll
        for (int i = 0; i < TM; ++i) {
            float2 o;
            o.x = mx[i][0] + mn[i][0] + bv.x;
            o.y = mx[i][1] + mn[i][1] + bv.y;
            *(float2*)(C + (size_t)(row0 + i) * N + col0) = o;
        }
        // Next tile's prologue writes buf 0; all reads of buf 0 completed before the
        // last staging sync, and buf-1 readers don't touch buf 0 -> no extra sync needed.
        // But a fast warp must not restage buf1 either before slow warps leave kt=63
        // compute on buf1 -> that store happens after the next tile's prologue sync. Safe.
        __syncthreads();
    }
}

extern "C" void kernel_launch(void* const* d_in, const int* in_sizes, int n_in,
                              void* d_out, int out_size)
{
    const float* x    = (const float*)d_in[0];   // [M, K]
    const float* w    = (const float*)d_in[1];   // [N, K]
    const float* bias = (const float*)d_in[2];   // [N]
    float* out = (float*)d_out;

    const int N = in_sizes[2];                  // 1024
    const int K = in_sizes[1] / N;              // 1024
    const int M = in_sizes[0] / K;              // 2048

    mam_dense_persistent<<<NUM_SMS, 256>>>(x, w, bias, out, M, N, K);
}